// round 2
// baseline (speedup 1.0000x reference)
#include <cuda_runtime.h>

#define B_   256
#define TP_  512
#define TQ_  64
#define DPQ_ 300
#define H_   256
#define G4_  1024

// ---------------- device scratch (no runtime allocation allowed) ----------------
__device__ float d_qproj[B_*TQ_*H_];        // 16.8 MB
__device__ float d_pW[B_*TP_*H_];           // 134 MB
__device__ float d_ppre[B_*TP_*G4_];        // 537 MB
__device__ float d_WihpT[DPQ_*G4_];
__device__ float d_WihqT[DPQ_*G4_];
__device__ float d_WhhT[H_*G4_];
__device__ float d_bias[G4_];
__device__ float d_hWr[B_*H_];
__device__ float d_hWhh[B_*G4_];
__device__ float d_ctx[B_*DPQ_];
__device__ float d_h[B_*H_];
__device__ float d_c[B_*H_];
__device__ unsigned g_cnt;
__device__ unsigned g_gen;

// ---------------- math helpers ----------------
__device__ __forceinline__ float tanh_fast(float x){
    // 1 - 2/(exp(2x)+1): 2 MUFU, ~1e-6 rel err, saturates correctly
    return 1.0f - 2.0f * __frcp_rn(__expf(2.0f*x) + 1.0f);
}
__device__ __forceinline__ float sigm(float x){
    return __frcp_rn(1.0f + __expf(-x));
}

// ---------------- software grid barrier (all CTAs resident: grid == #SMs) ----------------
__device__ __forceinline__ void grid_bar(int nctas){
    __syncthreads();
    if (threadIdx.x == 0){
        __threadfence();
        unsigned g = *(volatile unsigned*)&g_gen;
        unsigned prev = atomicAdd(&g_cnt, 1u);
        if (prev == (unsigned)(nctas - 1)){
            atomicExch(&g_cnt, 0u);
            __threadfence();
            atomicAdd(&g_gen, 1u);
        } else {
            while (*(volatile unsigned*)&g_gen == g) { __nanosleep(64); }
        }
        __threadfence();
    }
    __syncthreads();
}

// ---------------- K0: weight transposes + bias combine ----------------
__global__ void prep_kernel(const float* __restrict__ Wih, const float* __restrict__ Whh,
                            const float* __restrict__ bih, const float* __restrict__ bhh){
    int idx0 = blockIdx.x*blockDim.x + threadIdx.x;
    int stride = gridDim.x*blockDim.x;
    for (int i = idx0; i < DPQ_*G4_; i += stride){
        int k = i / G4_, n = i - k*G4_;
        d_WihpT[i] = Wih[n*600 + k];
        d_WihqT[i] = Wih[n*600 + 300 + k];
    }
    for (int i = idx0; i < H_*G4_; i += stride){
        int k = i / G4_, n = i - k*G4_;
        d_WhhT[i] = Whh[n*H_ + k];
    }
    for (int i = idx0; i < G4_; i += stride) d_bias[i] = bih[i] + bhh[i];
}

// ---------------- K1-3: tiled SGEMM  C[M,N] = A[M,K] * B[K,N] (row-major) ----------------
// 128x128 tile, BK=8, 256 threads, 8x8 micro-tile. Requires M%128==0, N%128==0, K%4==0.
__global__ void __launch_bounds__(256) sgemm128(const float* __restrict__ A,
                                                const float* __restrict__ Bm,
                                                float* __restrict__ C,
                                                int M, int N, int K){
    __shared__ float sA[8*128];
    __shared__ float sB[8*128];
    int tid = threadIdx.x;
    int m0 = blockIdx.y*128, n0 = blockIdx.x*128;
    int aRow = tid >> 1, aCol = (tid & 1)*4;
    int bRow = tid >> 5, bCol = (tid & 31)*4;
    int tx = tid & 15, ty = tid >> 4;
    float acc[8][8];
    #pragma unroll
    for (int i=0;i<8;i++)
        #pragma unroll
        for (int j=0;j<8;j++) acc[i][j] = 0.f;

    for (int k0 = 0; k0 < K; k0 += 8){
        float4 av = make_float4(0.f,0.f,0.f,0.f);
        float4 bv = make_float4(0.f,0.f,0.f,0.f);
        if (k0 + aCol < K)
            av = *(const float4*)(A + (size_t)(m0+aRow)*K + k0 + aCol);
        if (k0 + bRow < K)
            bv = *(const float4*)(Bm + (size_t)(k0+bRow)*N + n0 + bCol);
        __syncthreads();
        sA[(aCol+0)*128 + aRow] = av.x;
        sA[(aCol+1)*128 + aRow] = av.y;
        sA[(aCol+2)*128 + aRow] = av.z;
        sA[(aCol+3)*128 + aRow] = av.w;
        *(float4*)(sB + bRow*128 + bCol) = bv;
        __syncthreads();
        #pragma unroll
        for (int k=0;k<8;k++){
            float4 a0 = *(float4*)(sA + k*128 + ty*8);
            float4 a1 = *(float4*)(sA + k*128 + ty*8 + 4);
            float4 b0 = *(float4*)(sB + k*128 + tx*8);
            float4 b1 = *(float4*)(sB + k*128 + tx*8 + 4);
            float ar[8] = {a0.x,a0.y,a0.z,a0.w,a1.x,a1.y,a1.z,a1.w};
            float br[8] = {b0.x,b0.y,b0.z,b0.w,b1.x,b1.y,b1.z,b1.w};
            #pragma unroll
            for (int i=0;i<8;i++)
                #pragma unroll
                for (int j=0;j<8;j++)
                    acc[i][j] += ar[i]*br[j];
        }
    }
    #pragma unroll
    for (int i=0;i<8;i++){
        size_t row = (size_t)(m0 + ty*8 + i)*N + n0 + tx*8;
        #pragma unroll
        for (int j=0;j<8;j++) C[row + j] = acc[i][j];
    }
}

// ---------------- K4: persistent recurrent kernel ----------------
// smem union: P1: sA[16*65]=1040 | sB@1040..2064 (16*64)
//             P3: sA[16*33]=528 | sB@528 (16*128=2048) | sG@2576 (32*128=4096) -> 6672 total
//             P2: att[256] | sc[64]@256 | al[64]@320
__global__ void __launch_bounds__(256, 1) persist_kernel(
    const float* __restrict__ input_q, const float* __restrict__ mask_q,
    const float* __restrict__ mask_p,  const float* __restrict__ Wr,
    const float* __restrict__ b_att,   const float* __restrict__ w_att,
    float* __restrict__ out, int nctas)
{
    __shared__ float smem[6672];
    const int tid = threadIdx.x, bid = blockIdx.x;
    const int lane = tid & 31, warp = tid >> 5;

    // preload w_att into registers
    float wv[8];
    #pragma unroll
    for (int i=0;i<8;i++) wv[i] = w_att[lane + i*32];

    // zero initial state (every launch/replay)
    for (int i = bid*256 + tid; i < B_*H_; i += nctas*256){
        d_h[i] = 0.f;
        d_c[i] = 0.f;
    }
    grid_bar(nctas);

    for (int st = 0; st < TP_; st++){

        // ======== P1: [hWr | hWhh] = h @ [Wr | WhhT]  (256 x 1280, K=256) ========
        {
            float* sA = smem;           // [16][65] padded
            float* sB = smem + 1040;    // [16][64]
            const int ty = tid >> 4, tx = tid & 15;
            for (int tile = bid; tile < 80; tile += nctas){
                const int bt = tile / 20, jt = tile - bt*20;
                const int b0 = bt*64, j0 = jt*64;
                float acc[4][4];
                #pragma unroll
                for (int i=0;i<4;i++)
                    #pragma unroll
                    for (int j=0;j<4;j++) acc[i][j] = 0.f;
                for (int k0 = 0; k0 < H_; k0 += 16){
                    __syncthreads();
                    #pragma unroll
                    for (int i=0;i<4;i++){
                        int e = tid + i*256;
                        int bb = e >> 4, kk = e & 15;
                        sA[kk*65 + bb] = d_h[(b0+bb)*H_ + k0 + kk];
                        int k2 = e >> 6, jj = e & 63;
                        float w;
                        if (j0 < H_) w = Wr[(k0+k2)*H_ + j0 + jj];
                        else         w = d_WhhT[(k0+k2)*G4_ + (j0-H_) + jj];
                        sB[k2*64 + jj] = w;
                    }
                    __syncthreads();
                    #pragma unroll
                    for (int k=0;k<16;k++){
                        float ar[4];
                        #pragma unroll
                        for (int i=0;i<4;i++) ar[i] = sA[k*65 + ty*4 + i];
                        float4 b4 = *(float4*)(sB + k*64 + tx*4);
                        float br[4] = {b4.x,b4.y,b4.z,b4.w};
                        #pragma unroll
                        for (int i=0;i<4;i++)
                            #pragma unroll
                            for (int j=0;j<4;j++)
                                acc[i][j] += ar[i]*br[j];
                    }
                }
                #pragma unroll
                for (int i=0;i<4;i++){
                    int bb = b0 + ty*4 + i;
                    #pragma unroll
                    for (int j=0;j<4;j++){
                        int jg = j0 + tx*4 + j;
                        if (jg < H_) d_hWr[bb*H_ + jg] = acc[i][j] + b_att[jg];
                        else         d_hWhh[bb*G4_ + jg - H_] = acc[i][j];
                    }
                }
            }
        }
        grid_bar(nctas);

        // ======== P2: attention per batch element ========
        {
            float* att = smem;          // 256
            float* sSc = smem + 256;    // 64
            float* sAl = smem + 320;    // 64
            for (int b = bid; b < B_; b += nctas){
                __syncthreads();
                att[tid] = d_hWr[b*H_ + tid] + __ldcs(&d_pW[(b*TP_ + st)*H_ + tid]);
                __syncthreads();
                for (int tq = warp; tq < TQ_; tq += 8){
                    const float* qp = d_qproj + (b*TQ_ + tq)*H_;
                    float s = 0.f;
                    #pragma unroll
                    for (int i=0;i<8;i++){
                        int h = lane + i*32;
                        s += tanh_fast(qp[h] + att[h]) * wv[i];
                    }
                    #pragma unroll
                    for (int off=16; off; off >>= 1)
                        s += __shfl_xor_sync(0xffffffffu, s, off);
                    if (lane == 0) sSc[tq] = s;
                }
                __syncthreads();
                if (tid < 32){
                    float s0 = sSc[tid], s1 = sSc[tid+32];
                    if (!(mask_q[b*TQ_ + tid]      > 0.f)) s0 = -1e9f;
                    if (!(mask_q[b*TQ_ + tid + 32] > 0.f)) s1 = -1e9f;
                    float mx = fmaxf(s0, s1);
                    #pragma unroll
                    for (int off=16; off; off >>= 1)
                        mx = fmaxf(mx, __shfl_xor_sync(0xffffffffu, mx, off));
                    float e0 = __expf(s0 - mx), e1 = __expf(s1 - mx);
                    float sum = e0 + e1;
                    #pragma unroll
                    for (int off=16; off; off >>= 1)
                        sum += __shfl_xor_sync(0xffffffffu, sum, off);
                    float inv = __frcp_rn(sum);
                    sAl[tid]    = e0 * inv;
                    sAl[tid+32] = e1 * inv;
                }
                __syncthreads();
                for (int d = tid; d < DPQ_; d += 256){
                    float s = 0.f;
                    const float* iq = input_q + (size_t)b*TQ_*DPQ_ + d;
                    #pragma unroll 8
                    for (int tq = 0; tq < TQ_; tq++)
                        s += sAl[tq] * iq[tq*DPQ_];
                    d_ctx[b*DPQ_ + d] = s;
                }
            }
        }
        grid_bar(nctas);

        // ======== P3: gates = ctx @ WihqT (gathered i/f/g/o cols) + ppre + hWhh + bias;
        //              fused LSTM update + output store ========
        {
            float* sA = smem;           // [16][33] padded (32 batches)
            float* sB = smem + 528;     // [16][128]
            float* sG = smem + 2576;    // [32][128]
            const int ty = tid >> 5, tx = tid & 31;
            for (int tile = bid; tile < 64; tile += nctas){
                const int rt = tile >> 3, ht = tile & 7;
                const int b0 = rt*32, h0 = ht*32;
                float acc[4][4];
                #pragma unroll
                for (int i=0;i<4;i++)
                    #pragma unroll
                    for (int j=0;j<4;j++) acc[i][j] = 0.f;
                for (int k0 = 0; k0 < DPQ_; k0 += 16){
                    __syncthreads();
                    #pragma unroll
                    for (int i=0;i<2;i++){
                        int e = tid + i*256;
                        int bb = e >> 4, kk = e & 15;
                        sA[kk*33 + bb] = (k0+kk < DPQ_) ? d_ctx[(b0+bb)*DPQ_ + k0 + kk] : 0.f;
                    }
                    #pragma unroll
                    for (int i=0;i<8;i++){
                        int e = tid + i*256;
                        int kk = e >> 7, jj = e & 127;
                        int gcol = (jj >> 5)*H_ + h0 + (jj & 31);
                        sB[kk*128 + jj] = (k0+kk < DPQ_) ? d_WihqT[(k0+kk)*G4_ + gcol] : 0.f;
                    }
                    __syncthreads();
                    #pragma unroll
                    for (int k=0;k<16;k++){
                        float ar[4];
                        #pragma unroll
                        for (int i=0;i<4;i++) ar[i] = sA[k*33 + ty*4 + i];
                        float4 b4 = *(float4*)(sB + k*128 + tx*4);
                        float br[4] = {b4.x,b4.y,b4.z,b4.w};
                        #pragma unroll
                        for (int i=0;i<4;i++)
                            #pragma unroll
                            for (int j=0;j<4;j++)
                                acc[i][j] += ar[i]*br[j];
                    }
                }
                // epilogue: add ppre + hWhh + bias, stage gates in smem
                #pragma unroll
                for (int i=0;i<4;i++){
                    int r = ty*4 + i;
                    int b = b0 + r;
                    #pragma unroll
                    for (int j=0;j<4;j++){
                        int c = tx*4 + j;
                        int gcol = (c >> 5)*H_ + h0 + (c & 31);
                        float v = acc[i][j]
                                + __ldcs(&d_ppre[((size_t)b*TP_ + st)*G4_ + gcol])
                                + d_hWhh[b*G4_ + gcol]
                                + d_bias[gcol];
                        sG[r*128 + c] = v;
                    }
                }
                __syncthreads();
                // fused LSTM update: 32 batches x 32 h
                #pragma unroll
                for (int i=0;i<4;i++){
                    int e = tid + i*256;
                    int r = e >> 5, hh = e & 31;
                    int b = b0 + r, hg = h0 + hh;
                    float ig = sigm(sG[r*128 + hh]);
                    float fg = sigm(sG[r*128 + 32 + hh]);
                    float gg = tanh_fast(sG[r*128 + 64 + hh]);
                    float og = sigm(sG[r*128 + 96 + hh]);
                    float c_old = d_c[b*H_ + hg];
                    float h_old = d_h[b*H_ + hg];
                    float c_new = fg*c_old + ig*gg;
                    float h_new = og * tanh_fast(c_new);
                    float m = mask_p[b*TP_ + st];
                    h_new = h_new*m + h_old*(1.f-m);
                    c_new = c_new*m + c_old*(1.f-m);
                    d_h[b*H_ + hg] = h_new;
                    d_c[b*H_ + hg] = c_new;
                    out[((size_t)b*TP_ + st)*H_ + hg] = h_new;
                }
            }
        }
        grid_bar(nctas);
    }
}

// ---------------- launch ----------------
extern "C" void kernel_launch(void* const* d_in, const int* in_sizes, int n_in,
                              void* d_out, int out_size) {
    const float* input_p = (const float*)d_in[0];
    const float* mask_p  = (const float*)d_in[1];
    const float* input_q = (const float*)d_in[2];
    const float* mask_q  = (const float*)d_in[3];
    const float* Wq      = (const float*)d_in[4];
    const float* Wp      = (const float*)d_in[5];
    const float* Wr      = (const float*)d_in[6];
    const float* b_att   = (const float*)d_in[7];
    const float* w_att   = (const float*)d_in[8];
    const float* W_ih    = (const float*)d_in[9];
    const float* W_hh    = (const float*)d_in[10];
    const float* b_ih    = (const float*)d_in[11];
    const float* b_hh    = (const float*)d_in[12];
    float* out = (float*)d_out;

    int dev = 0; cudaGetDevice(&dev);
    int nsm = 0; cudaDeviceGetAttribute(&nsm, cudaDevAttrMultiProcessorCount, dev);
    if (nsm <= 0) nsm = 148;

    float *p_qproj, *p_pW, *p_ppre, *p_WihpT;
    cudaGetSymbolAddress((void**)&p_qproj, d_qproj);
    cudaGetSymbolAddress((void**)&p_pW,    d_pW);
    cudaGetSymbolAddress((void**)&p_ppre,  d_ppre);
    cudaGetSymbolAddress((void**)&p_WihpT, d_WihpT);

    prep_kernel<<<1200, 256>>>(W_ih, W_hh, b_ih, b_hh);

    // q_proj = input_q(16384x300) @ Wq(300x256)
    sgemm128<<<dim3(2,128), 256>>>(input_q, Wq, p_qproj, B_*TQ_, H_, DPQ_);
    // pW = input_p(131072x300) @ Wp(300x256)
    sgemm128<<<dim3(2,1024), 256>>>(input_p, Wp, p_pW, B_*TP_, H_, DPQ_);
    // ppre = input_p(131072x300) @ WihpT(300x1024)
    sgemm128<<<dim3(8,1024), 256>>>(input_p, p_WihpT, p_ppre, B_*TP_, G4_, DPQ_);

    persist_kernel<<<nsm, 256>>>(input_q, mask_q, mask_p, Wr, b_att, w_att, out, nsm);
}

// round 3
// speedup vs baseline: 2.2026x; 2.2026x over previous
#include <cuda_runtime.h>

#define B_   256
#define TP_  512
#define TQ_  64
#define DPQ_ 300
#define KP_  320     // padded K for 300-dim GEMMs
#define H_   256
#define G4_  1024

// ---------------- device scratch ----------------
__device__ float d_qproj[B_*TQ_*H_];        // [b*64+tq][h]
__device__ float d_pW[TP_*B_*H_];           // time-major [st][b][h]
__device__ float d_ppre[TP_*B_*G4_];        // time-major [st][b][j]  (permuted gate cols)
__device__ float d_W2T[1280*H_];            // n-major [n][k]; n>=256 permuted gate cols
__device__ float d_WqT2[G4_*KP_];           // n-major permuted [j][k], k>=300 zero
__device__ float d_WihpT2[G4_*KP_];         // n-major permuted [j][k]
__device__ float d_WqTn[H_*KP_];            // Wq^T [n][k]
__device__ float d_WpTn[H_*KP_];            // Wp^T [n][k]
__device__ float d_bias[G4_];               // permuted
__device__ float d_hWr[B_*H_];
__device__ float d_hWhh[B_*G4_];            // permuted cols
__device__ float d_ctx[B_*KP_];             // padded, pads zero
__device__ float d_h[B_*H_];
__device__ float d_c[B_*H_];
__device__ unsigned g_cnt;
__device__ unsigned g_gen;

// ---------------- helpers ----------------
__device__ __forceinline__ float tanha(float x){
    float y; asm("tanh.approx.f32 %0, %1;" : "=f"(y) : "f"(x)); return y;
}
__device__ __forceinline__ float sigm2(float x){
    return fmaf(tanha(0.5f*x), 0.5f, 0.5f);
}
__device__ __forceinline__ float to_tf32(float x){
    unsigned u; asm("cvt.rna.tf32.f32 %0, %1;" : "=r"(u) : "f"(x));
    return __uint_as_float(u);
}
__device__ __forceinline__ void mma8(float* d, unsigned a0, unsigned a1, unsigned a2, unsigned a3,
                                     unsigned b0, unsigned b1){
    asm volatile("mma.sync.aligned.m16n8k8.row.col.f32.tf32.tf32.f32 "
                 "{%0,%1,%2,%3},{%4,%5,%6,%7},{%8,%9},{%0,%1,%2,%3};"
                 : "+f"(d[0]), "+f"(d[1]), "+f"(d[2]), "+f"(d[3])
                 : "r"(a0), "r"(a1), "r"(a2), "r"(a3), "r"(b0), "r"(b1));
}

// stage loader: 64 rows x 32 k into sA/sB (stride 36), A k-guarded
__device__ __forceinline__ void stage_load(const float* __restrict__ Ag, int lda,
                                           const float* __restrict__ Bg, int ldb,
                                           float* sA, float* sB, int tid, int krem){
    #pragma unroll
    for (int i = 0; i < 2; i++){
        int f = tid + i*256;
        int row = f >> 3, c4 = (f & 7)*4;
        float4 va = make_float4(0.f,0.f,0.f,0.f);
        if (c4 < krem) va = *(const float4*)(Ag + (size_t)row*lda + c4);
        *(float4*)(sA + row*36 + c4) = va;
        float4 vb = *(const float4*)(Bg + (size_t)row*ldb + c4);
        *(float4*)(sB + row*36 + c4) = vb;
    }
}

// 32-k chunk of mma on staged tiles; warp tile 32x16 (2x2 frags of m16n8)
__device__ __forceinline__ void mma_tile_step(const float* sA, const float* sB,
                                              int m0w, int n0w, int g, int tg,
                                              float acc[2][2][4]){
    #pragma unroll
    for (int kk = 0; kk < 32; kk += 8){
        const float* pa = sA + kk + tg;
        const float* pb = sB + kk + tg;
        unsigned a00 = __float_as_uint(pa[(m0w+g)*36]);
        unsigned a01 = __float_as_uint(pa[(m0w+g+8)*36]);
        unsigned a02 = __float_as_uint(pa[(m0w+g)*36 + 4]);
        unsigned a03 = __float_as_uint(pa[(m0w+g+8)*36 + 4]);
        unsigned a10 = __float_as_uint(pa[(m0w+16+g)*36]);
        unsigned a11 = __float_as_uint(pa[(m0w+24+g)*36]);
        unsigned a12 = __float_as_uint(pa[(m0w+16+g)*36 + 4]);
        unsigned a13 = __float_as_uint(pa[(m0w+24+g)*36 + 4]);
        unsigned b00 = __float_as_uint(pb[(n0w+g)*36]);
        unsigned b01 = __float_as_uint(pb[(n0w+g)*36 + 4]);
        unsigned b10 = __float_as_uint(pb[(n0w+8+g)*36]);
        unsigned b11 = __float_as_uint(pb[(n0w+8+g)*36 + 4]);
        mma8(acc[0][0], a00,a01,a02,a03, b00,b01);
        mma8(acc[0][1], a00,a01,a02,a03, b10,b11);
        mma8(acc[1][0], a10,a11,a12,a13, b00,b01);
        mma8(acc[1][1], a10,a11,a12,a13, b10,b11);
    }
}

// ---------------- grid barrier ----------------
__device__ __forceinline__ void grid_bar(int nctas){
    __syncthreads();
    if (threadIdx.x == 0){
        __threadfence();
        unsigned g = *(volatile unsigned*)&g_gen;
        unsigned prev = atomicAdd(&g_cnt, 1u);
        if (prev == (unsigned)(nctas - 1)){
            atomicExch(&g_cnt, 0u);
            __threadfence();
            atomicAdd(&g_gen, 1u);
        } else {
            while (*(volatile unsigned*)&g_gen == g) { __nanosleep(32); }
        }
        __threadfence();
    }
    __syncthreads();
}

// gate-column permutation: j -> actual gate column
__device__ __forceinline__ int gperm(int j){ return (j & 3)*H_ + (j >> 2); }

// ---------------- K0: weight prep (transpose, permute, tf32-round, pad) ----------------
__global__ void prep_kernel(const float* __restrict__ Wq, const float* __restrict__ Wp,
                            const float* __restrict__ Wr, const float* __restrict__ Wih,
                            const float* __restrict__ Whh,
                            const float* __restrict__ bih, const float* __restrict__ bhh){
    int idx0 = blockIdx.x*blockDim.x + threadIdx.x;
    int stride = gridDim.x*blockDim.x;
    for (int i = idx0; i < 1280*H_; i += stride){
        int n = i / H_, k = i - n*H_;
        float v = (n < H_) ? Wr[k*H_ + n] : Whh[gperm(n - H_)*H_ + k];
        d_W2T[i] = to_tf32(v);
    }
    for (int i = idx0; i < G4_*KP_; i += stride){
        int j = i / KP_, k = i - j*KP_;
        int a = gperm(j);
        d_WqT2[i]   = (k < DPQ_) ? to_tf32(Wih[a*600 + 300 + k]) : 0.f;
        d_WihpT2[i] = (k < DPQ_) ? to_tf32(Wih[a*600 + k])       : 0.f;
    }
    for (int i = idx0; i < H_*KP_; i += stride){
        int n = i / KP_, k = i - n*KP_;
        d_WqTn[i] = (k < DPQ_) ? to_tf32(Wq[k*H_ + n]) : 0.f;
        d_WpTn[i] = (k < DPQ_) ? to_tf32(Wp[k*H_ + n]) : 0.f;
    }
    for (int j = idx0; j < G4_; j += stride){
        int a = gperm(j);
        d_bias[j] = bih[a] + bhh[a];
    }
}

// ---------------- generic tf32 GEMM: C[M,N] = A[M,K] @ BT[N,K]^T ----------------
// 64x64 CTA tile, 256 threads, 8 warps (2x4), warp tile 32x16.
// mode 0: C[m*N+n]; mode 1: time-major C[((m&511)*256 + (m>>9))*N + n]
__global__ void __launch_bounds__(256) gemm64_tf32(const float* __restrict__ A, int lda, int K,
                                                   const float* __restrict__ BT, int ldb,
                                                   float* __restrict__ C, int N, int mode){
    __shared__ float sA[64*36];
    __shared__ float sB[64*36];
    const int tid = threadIdx.x, lane = tid & 31, warp = tid >> 5;
    const int g = lane >> 2, tg = lane & 3;
    const int m0 = blockIdx.y*64, n0 = blockIdx.x*64;
    const int m0w = (warp & 1)*32, n0w = (warp >> 1)*16;
    float acc[2][2][4] = {};
    const int nst = (K + 31)/32;
    for (int s = 0; s < nst; s++){
        int k0 = s*32;
        __syncthreads();
        stage_load(A + (size_t)m0*lda + k0, lda, BT + (size_t)n0*ldb + k0, ldb,
                   sA, sB, tid, K - k0);
        __syncthreads();
        mma_tile_step(sA, sB, m0w, n0w, g, tg, acc);
    }
    #pragma unroll
    for (int fm = 0; fm < 2; fm++)
        #pragma unroll
        for (int fn = 0; fn < 2; fn++){
            int r = m0 + m0w + fm*16 + g;
            int c = n0 + n0w + fn*8 + tg*2;
            int m1 = r, m2 = r + 8;
            if (mode){
                m1 = (r & (TP_-1))*B_ + (r >> 9);
                m2 = ((r+8) & (TP_-1))*B_ + ((r+8) >> 9);
            }
            *(float2*)(C + (size_t)m1*N + c) = make_float2(acc[fm][fn][0], acc[fm][fn][1]);
            *(float2*)(C + (size_t)m2*N + c) = make_float2(acc[fm][fn][2], acc[fm][fn][3]);
        }
}

// ---------------- persistent recurrent kernel ----------------
__global__ void __launch_bounds__(256, 1) persist_kernel(
    const float* __restrict__ input_q, const float* __restrict__ mask_q,
    const float* __restrict__ mask_p,  const float* __restrict__ b_att,
    const float* __restrict__ w_att,   float* __restrict__ out, int nctas)
{
    __shared__ float sA[64*36];
    __shared__ float sB[64*36];
    __shared__ float sG[64*68];
    const int tid = threadIdx.x, bid = blockIdx.x;
    const int lane = tid & 31, warp = tid >> 5;
    const int g = lane >> 2, tg = lane & 3;
    const int m0w = (warp & 1)*32, n0w = (warp >> 1)*16;

    float wv[8];
    #pragma unroll
    for (int i = 0; i < 8; i++) wv[i] = w_att[lane + i*32];

    // init state + ctx pads (every launch/replay)
    for (int i = bid*256 + tid; i < B_*H_; i += nctas*256){ d_h[i] = 0.f; d_c[i] = 0.f; }
    for (int i = bid*256 + tid; i < B_*KP_; i += nctas*256) d_ctx[i] = 0.f;
    grid_bar(nctas);

    for (int st = 0; st < TP_; st++){

        // ======== P1: [hWr | hWhh] = h[256,256] @ W2T^T (N=1280), tensor cores ========
        if (bid < 80){
            const int tm = bid / 20, tn = bid - tm*20;
            const int b0 = tm*64, n0 = tn*64;
            float acc[2][2][4] = {};
            #pragma unroll 1
            for (int s = 0; s < 8; s++){
                int k0 = s*32;
                __syncthreads();
                stage_load(d_h + (size_t)b0*H_ + k0, H_, d_W2T + (size_t)n0*H_ + k0, H_,
                           sA, sB, tid, 32);
                __syncthreads();
                mma_tile_step(sA, sB, m0w, n0w, g, tg, acc);
            }
            const bool isR = (n0 < H_);
            #pragma unroll
            for (int fm = 0; fm < 2; fm++)
                #pragma unroll
                for (int fn = 0; fn < 2; fn++){
                    int r = b0 + m0w + fm*16 + g;
                    int c = n0 + n0w + fn*8 + tg*2;
                    if (isR){
                        float ba0 = b_att[c], ba1 = b_att[c+1];
                        *(float2*)(d_hWr + r*H_ + c)     = make_float2(acc[fm][fn][0]+ba0, acc[fm][fn][1]+ba1);
                        *(float2*)(d_hWr + (r+8)*H_ + c) = make_float2(acc[fm][fn][2]+ba0, acc[fm][fn][3]+ba1);
                    } else {
                        int j = c - H_;
                        *(float2*)(d_hWhh + r*G4_ + j)     = make_float2(acc[fm][fn][0], acc[fm][fn][1]);
                        *(float2*)(d_hWhh + (r+8)*G4_ + j) = make_float2(acc[fm][fn][2], acc[fm][fn][3]);
                    }
                }
        }
        grid_bar(nctas);

        // ======== P2: attention per batch ========
        {
            float* att = sA;            // 256
            float* sSc = sA + 256;      // 64
            float* sAl = sA + 320;      // 64
            for (int b = bid; b < B_; b += nctas){
                __syncthreads();
                att[tid] = d_hWr[b*H_ + tid] + d_pW[((size_t)st*B_ + b)*H_ + tid];
                __syncthreads();
                for (int tq = warp; tq < TQ_; tq += 8){
                    const float* qp = d_qproj + (size_t)(b*TQ_ + tq)*H_;
                    float s = 0.f;
                    #pragma unroll
                    for (int i = 0; i < 8; i++){
                        int h = lane + i*32;
                        s += tanha(qp[h] + att[h]) * wv[i];
                    }
                    #pragma unroll
                    for (int off = 16; off; off >>= 1)
                        s += __shfl_xor_sync(0xffffffffu, s, off);
                    if (lane == 0) sSc[tq] = s;
                }
                __syncthreads();
                if (tid < 32){
                    float s0 = sSc[tid], s1 = sSc[tid+32];
                    if (!(mask_q[b*TQ_ + tid]      > 0.f)) s0 = -1e9f;
                    if (!(mask_q[b*TQ_ + tid + 32] > 0.f)) s1 = -1e9f;
                    float mx = fmaxf(s0, s1);
                    #pragma unroll
                    for (int off = 16; off; off >>= 1)
                        mx = fmaxf(mx, __shfl_xor_sync(0xffffffffu, mx, off));
                    float e0 = __expf(s0 - mx), e1 = __expf(s1 - mx);
                    float sum = e0 + e1;
                    #pragma unroll
                    for (int off = 16; off; off >>= 1)
                        sum += __shfl_xor_sync(0xffffffffu, sum, off);
                    float inv = __frcp_rn(sum);
                    sAl[tid]      = e0 * inv;
                    sAl[tid + 32] = e1 * inv;
                }
                __syncthreads();
                for (int d = tid; d < DPQ_; d += 256){
                    float s = 0.f;
                    const float* iq = input_q + (size_t)b*TQ_*DPQ_ + d;
                    #pragma unroll 8
                    for (int tq = 0; tq < TQ_; tq++)
                        s += sAl[tq] * iq[tq*DPQ_];
                    d_ctx[b*KP_ + d] = s;
                }
            }
        }
        grid_bar(nctas);

        // ======== P3: gates = ctx @ WqT2^T (permuted cols) + ppre + hWhh + bias; LSTM ========
        if (bid < 64){
            const int tm = bid >> 4, tn = bid & 15;
            const int b0 = tm*64, j0 = tn*64;
            float acc[2][2][4] = {};
            #pragma unroll 1
            for (int s = 0; s < 10; s++){
                int k0 = s*32;
                __syncthreads();
                stage_load(d_ctx + (size_t)b0*KP_ + k0, KP_, d_WqT2 + (size_t)j0*KP_ + k0, KP_,
                           sA, sB, tid, 32);
                __syncthreads();
                mma_tile_step(sA, sB, m0w, n0w, g, tg, acc);
            }
            #pragma unroll
            for (int fm = 0; fm < 2; fm++)
                #pragma unroll
                for (int fn = 0; fn < 2; fn++){
                    int rl = m0w + fm*16 + g;
                    int cl = n0w + fn*8 + tg*2;
                    sG[rl*68 + cl]       = acc[fm][fn][0];
                    sG[rl*68 + cl + 1]   = acc[fm][fn][1];
                    sG[(rl+8)*68 + cl]   = acc[fm][fn][2];
                    sG[(rl+8)*68 + cl+1] = acc[fm][fn][3];
                }
            __syncthreads();
            #pragma unroll
            for (int u = 0; u < 4; u++){
                int idx = tid + u*256;          // 0..1023 = 64 b x 16 h
                int bl = idx >> 4, hl = idx & 15;
                int b = b0 + bl;
                int j = j0 + hl*4;
                int hg = (j0 >> 2) + hl;
                float4 gm = *(float4*)(sG + bl*68 + hl*4);
                float4 pp = __ldcs((const float4*)(d_ppre + ((size_t)st*B_ + b)*G4_ + j));
                float4 hh = *(const float4*)(d_hWhh + (size_t)b*G4_ + j);
                float4 bb = *(const float4*)(d_bias + j);
                float gi = gm.x + pp.x + hh.x + bb.x;
                float gf = gm.y + pp.y + hh.y + bb.y;
                float gg = gm.z + pp.z + hh.z + bb.z;
                float go = gm.w + pp.w + hh.w + bb.w;
                float ig = sigm2(gi), fg = sigm2(gf);
                float gt = tanha(gg), og = sigm2(go);
                float c_old = d_c[b*H_ + hg];
                float h_old = d_h[b*H_ + hg];
                float c_new = fg*c_old + ig*gt;
                float h_new = og * tanha(c_new);
                float m = mask_p[b*TP_ + st];
                h_new = h_new*m + h_old*(1.f - m);
                c_new = c_new*m + c_old*(1.f - m);
                d_h[b*H_ + hg] = h_new;
                d_c[b*H_ + hg] = c_new;
                out[((size_t)b*TP_ + st)*H_ + hg] = h_new;
            }
        }
        grid_bar(nctas);
    }
}

// ---------------- launch ----------------
extern "C" void kernel_launch(void* const* d_in, const int* in_sizes, int n_in,
                              void* d_out, int out_size) {
    const float* input_p = (const float*)d_in[0];
    const float* mask_p  = (const float*)d_in[1];
    const float* input_q = (const float*)d_in[2];
    const float* mask_q  = (const float*)d_in[3];
    const float* Wq      = (const float*)d_in[4];
    const float* Wp      = (const float*)d_in[5];
    const float* Wr      = (const float*)d_in[6];
    const float* b_att   = (const float*)d_in[7];
    const float* w_att   = (const float*)d_in[8];
    const float* W_ih    = (const float*)d_in[9];
    const float* W_hh    = (const float*)d_in[10];
    const float* b_ih    = (const float*)d_in[11];
    const float* b_hh    = (const float*)d_in[12];
    float* out = (float*)d_out;

    int dev = 0; cudaGetDevice(&dev);
    int nsm = 0; cudaDeviceGetAttribute(&nsm, cudaDevAttrMultiProcessorCount, dev);
    if (nsm <= 0) nsm = 148;

    float *p_qproj, *p_pW, *p_ppre, *p_WqTn, *p_WpTn, *p_WihpT2;
    cudaGetSymbolAddress((void**)&p_qproj,   d_qproj);
    cudaGetSymbolAddress((void**)&p_pW,      d_pW);
    cudaGetSymbolAddress((void**)&p_ppre,    d_ppre);
    cudaGetSymbolAddress((void**)&p_WqTn,    d_WqTn);
    cudaGetSymbolAddress((void**)&p_WpTn,    d_WpTn);
    cudaGetSymbolAddress((void**)&p_WihpT2,  d_WihpT2);

    prep_kernel<<<512, 256>>>(Wq, Wp, Wr, W_ih, W_hh, b_ih, b_hh);

    // q_proj[16384,256] = input_q @ Wq            (mode 0)
    gemm64_tf32<<<dim3(4, 256), 256>>>(input_q, DPQ_, DPQ_, p_WqTn, KP_, p_qproj, H_, 0);
    // pW[st][b][256] = input_p @ Wp               (mode 1: time-major)
    gemm64_tf32<<<dim3(4, 2048), 256>>>(input_p, DPQ_, DPQ_, p_WpTn, KP_, p_pW, H_, 1);
    // ppre[st][b][1024] = input_p @ Wihp^T (permuted cols, mode 1)
    gemm64_tf32<<<dim3(16, 2048), 256>>>(input_p, DPQ_, DPQ_, p_WihpT2, KP_, p_ppre, G4_, 1);

    persist_kernel<<<nsm, 256>>>(input_q, mask_q, mask_p, b_att, w_att, out, nsm);
}

// round 5
// speedup vs baseline: 2.5723x; 1.1678x over previous
#include <cuda_runtime.h>

#define B_   256
#define TP_  512
#define TQ_  64
#define DPQ_ 300
#define KP_  320     // padded K for 300-dim GEMMs
#define H_   256
#define G4_  1024

// smem layout (floats) for persist kernel
#define RING_SLOT_ 2304        // 64 rows x 36
#define W_OFF_     9216        // after 4 ring slots
#define SG_OFF_    29952       // after P3 weight tile (64*324)
#define SMEM_FLOATS_ 34304     // + sG 64*68 -> 137216 bytes

// ---------------- device scratch ----------------
__device__ float d_qproj[B_*TQ_*H_];        // [b*64+tq][h]
__device__ float d_pW[TP_*B_*H_];           // time-major [st][b][h]
__device__ float d_ppre[TP_*B_*G4_];        // time-major [st][b][j] (permuted gate cols)
__device__ float d_W2T[1280*H_];            // n-major [n][k]; n>=256 = permuted Whh cols
__device__ float d_WqT2[G4_*KP_];           // n-major permuted [j][k], k>=300 zero
__device__ float d_WihpT2[G4_*KP_];
__device__ float d_WqTn[H_*KP_];
__device__ float d_WpTn[H_*KP_];
__device__ float d_bias[G4_];
__device__ float d_hWr[B_*H_];
__device__ float d_hWhh[B_*G4_];
__device__ float d_ctx[B_*KP_];
__device__ float d_h[B_*H_];
__device__ float d_c[B_*H_];
__device__ unsigned g_cnt;
__device__ unsigned g_gen;

// ---------------- helpers ----------------
__device__ __forceinline__ float tanha(float x){
    float y; asm("tanh.approx.f32 %0, %1;" : "=f"(y) : "f"(x)); return y;
}
__device__ __forceinline__ float sigm2(float x){
    return fmaf(tanha(0.5f*x), 0.5f, 0.5f);
}
__device__ __forceinline__ float to_tf32(float x){
    unsigned u; asm("cvt.rna.tf32.f32 %0, %1;" : "=r"(u) : "f"(x));
    return __uint_as_float(u);
}
__device__ __forceinline__ void mma8(float* d, unsigned a0, unsigned a1, unsigned a2, unsigned a3,
                                     unsigned b0, unsigned b1){
    asm volatile("mma.sync.aligned.m16n8k8.row.col.f32.tf32.tf32.f32 "
                 "{%0,%1,%2,%3},{%4,%5,%6,%7},{%8,%9},{%0,%1,%2,%3};"
                 : "+f"(d[0]), "+f"(d[1]), "+f"(d[2]), "+f"(d[3])
                 : "r"(a0), "r"(a1), "r"(a2), "r"(a3), "r"(b0), "r"(b1));
}
__device__ __forceinline__ void cpa16(unsigned s, const float* g){
    asm volatile("cp.async.cg.shared.global [%0], [%1], 16;" :: "r"(s), "l"(g));
}
#define CP_COMMIT() asm volatile("cp.async.commit_group;" ::: "memory")
#define CP_WAIT2()  asm volatile("cp.async.wait_group 2;"  ::: "memory")
#define CP_WAIT0()  asm volatile("cp.async.wait_group 0;"  ::: "memory")

// ---------------- PROVEN grid barrier (R3) ----------------
__device__ __forceinline__ void grid_bar(int nctas){
    __syncthreads();
    if (threadIdx.x == 0){
        __threadfence();
        unsigned g = *(volatile unsigned*)&g_gen;
        unsigned prev = atomicAdd(&g_cnt, 1u);
        if (prev == (unsigned)(nctas - 1)){
            atomicExch(&g_cnt, 0u);
            __threadfence();
            atomicAdd(&g_gen, 1u);
        } else {
            while (*(volatile unsigned*)&g_gen == g) { __nanosleep(32); }
        }
        __threadfence();
    }
    __syncthreads();
}

// gate-column permutation: j -> actual gate column
__device__ __forceinline__ int gperm(int j){ return (j & 3)*H_ + (j >> 2); }

// ---------------- K0: weight prep ----------------
__global__ void prep_kernel(const float* __restrict__ Wq, const float* __restrict__ Wp,
                            const float* __restrict__ Wr, const float* __restrict__ Wih,
                            const float* __restrict__ Whh,
                            const float* __restrict__ bih, const float* __restrict__ bhh){
    int idx0 = blockIdx.x*blockDim.x + threadIdx.x;
    int stride = gridDim.x*blockDim.x;
    for (int i = idx0; i < 1280*H_; i += stride){
        int n = i / H_, k = i - n*H_;
        float v = (n < H_) ? Wr[k*H_ + n] : Whh[gperm(n - H_)*H_ + k];
        d_W2T[i] = to_tf32(v);
    }
    for (int i = idx0; i < G4_*KP_; i += stride){
        int j = i / KP_, k = i - j*KP_;
        int a = gperm(j);
        d_WqT2[i]   = (k < DPQ_) ? to_tf32(Wih[a*600 + 300 + k]) : 0.f;
        d_WihpT2[i] = (k < DPQ_) ? to_tf32(Wih[a*600 + k])       : 0.f;
    }
    for (int i = idx0; i < H_*KP_; i += stride){
        int n = i / KP_, k = i - n*KP_;
        d_WqTn[i] = (k < DPQ_) ? to_tf32(Wq[k*H_ + n]) : 0.f;
        d_WpTn[i] = (k < DPQ_) ? to_tf32(Wp[k*H_ + n]) : 0.f;
    }
    for (int j = idx0; j < G4_; j += stride){
        int a = gperm(j);
        d_bias[j] = bih[a] + bhh[a];
    }
}

// ---------------- upfront tf32 GEMM (unchanged from R3, passing) ----------------
__device__ __forceinline__ void stage_load(const float* __restrict__ Ag, int lda,
                                           const float* __restrict__ Bg, int ldb,
                                           float* sA, float* sB, int tid, int krem){
    #pragma unroll
    for (int i = 0; i < 2; i++){
        int f = tid + i*256;
        int row = f >> 3, c4 = (f & 7)*4;
        float4 va = make_float4(0.f,0.f,0.f,0.f);
        if (c4 < krem) va = *(const float4*)(Ag + (size_t)row*lda + c4);
        *(float4*)(sA + row*36 + c4) = va;
        float4 vb = *(const float4*)(Bg + (size_t)row*ldb + c4);
        *(float4*)(sB + row*36 + c4) = vb;
    }
}
__device__ __forceinline__ void mma_tile_step(const float* sA, const float* sB,
                                              int m0w, int n0w, int g, int tg,
                                              float acc[2][2][4]){
    #pragma unroll
    for (int kk = 0; kk < 32; kk += 8){
        const float* pa = sA + kk + tg;
        const float* pb = sB + kk + tg;
        unsigned a00 = __float_as_uint(pa[(m0w+g)*36]);
        unsigned a01 = __float_as_uint(pa[(m0w+g+8)*36]);
        unsigned a02 = __float_as_uint(pa[(m0w+g)*36 + 4]);
        unsigned a03 = __float_as_uint(pa[(m0w+g+8)*36 + 4]);
        unsigned a10 = __float_as_uint(pa[(m0w+16+g)*36]);
        unsigned a11 = __float_as_uint(pa[(m0w+24+g)*36]);
        unsigned a12 = __float_as_uint(pa[(m0w+16+g)*36 + 4]);
        unsigned a13 = __float_as_uint(pa[(m0w+24+g)*36 + 4]);
        unsigned b00 = __float_as_uint(pb[(n0w+g)*36]);
        unsigned b01 = __float_as_uint(pb[(n0w+g)*36 + 4]);
        unsigned b10 = __float_as_uint(pb[(n0w+8+g)*36]);
        unsigned b11 = __float_as_uint(pb[(n0w+8+g)*36 + 4]);
        mma8(acc[0][0], a00,a01,a02,a03, b00,b01);
        mma8(acc[0][1], a00,a01,a02,a03, b10,b11);
        mma8(acc[1][0], a10,a11,a12,a13, b00,b01);
        mma8(acc[1][1], a10,a11,a12,a13, b10,b11);
    }
}
__global__ void __launch_bounds__(256) gemm64_tf32(const float* __restrict__ A, int lda, int K,
                                                   const float* __restrict__ BT, int ldb,
                                                   float* __restrict__ C, int N, int mode){
    __shared__ float sA[64*36];
    __shared__ float sB[64*36];
    const int tid = threadIdx.x, lane = tid & 31, warp = tid >> 5;
    const int g = lane >> 2, tg = lane & 3;
    const int m0 = blockIdx.y*64, n0 = blockIdx.x*64;
    const int m0w = (warp & 1)*32, n0w = (warp >> 1)*16;
    float acc[2][2][4] = {};
    const int nst = (K + 31)/32;
    for (int s = 0; s < nst; s++){
        int k0 = s*32;
        __syncthreads();
        stage_load(A + (size_t)m0*lda + k0, lda, BT + (size_t)n0*ldb + k0, ldb,
                   sA, sB, tid, K - k0);
        __syncthreads();
        mma_tile_step(sA, sB, m0w, n0w, g, tg, acc);
    }
    #pragma unroll
    for (int fm = 0; fm < 2; fm++)
        #pragma unroll
        for (int fn = 0; fn < 2; fn++){
            int r = m0 + m0w + fm*16 + g;
            int c = n0 + n0w + fn*8 + tg*2;
            int m1 = r, m2 = r + 8;
            if (mode){
                m1 = (r & (TP_-1))*B_ + (r >> 9);
                m2 = ((r+8) & (TP_-1))*B_ + ((r+8) >> 9);
            }
            *(float2*)(C + (size_t)m1*N + c) = make_float2(acc[fm][fn][0], acc[fm][fn][1]);
            *(float2*)(C + (size_t)m2*N + c) = make_float2(acc[fm][fn][2], acc[fm][fn][3]);
        }
}

// ---------------- resident-B mma + cp.async ring GEMM ----------------
template<int LB>
__device__ __forceinline__ void mma_step_resB(const float* sAslot, const float* sW, int koff,
                                              int m0w, int n0w, int g, int tg, float acc[2][2][4]){
    #pragma unroll
    for (int kk = 0; kk < 32; kk += 8){
        const float* pa = sAslot + kk + tg;
        const float* pb = sW + koff + kk + tg;
        unsigned a00 = __float_as_uint(pa[(m0w+g)*36]);
        unsigned a01 = __float_as_uint(pa[(m0w+g+8)*36]);
        unsigned a02 = __float_as_uint(pa[(m0w+g)*36 + 4]);
        unsigned a03 = __float_as_uint(pa[(m0w+g+8)*36 + 4]);
        unsigned a10 = __float_as_uint(pa[(m0w+16+g)*36]);
        unsigned a11 = __float_as_uint(pa[(m0w+24+g)*36]);
        unsigned a12 = __float_as_uint(pa[(m0w+16+g)*36 + 4]);
        unsigned a13 = __float_as_uint(pa[(m0w+24+g)*36 + 4]);
        unsigned b00 = __float_as_uint(pb[(n0w+g)*LB]);
        unsigned b01 = __float_as_uint(pb[(n0w+g)*LB + 4]);
        unsigned b10 = __float_as_uint(pb[(n0w+8+g)*LB]);
        unsigned b11 = __float_as_uint(pb[(n0w+8+g)*LB + 4]);
        mma8(acc[0][0], a00,a01,a02,a03, b00,b01);
        mma8(acc[0][1], a00,a01,a02,a03, b10,b11);
        mma8(acc[1][0], a10,a11,a12,a13, b00,b01);
        mma8(acc[1][1], a10,a11,a12,a13, b10,b11);
    }
}

template<int LB, int NST>
__device__ __forceinline__ void gemm_ring(const float* __restrict__ Ag, int lda,
                                          float* sm, unsigned sbase, int tid,
                                          int m0w, int n0w, int g, int tg, float acc[2][2][4]){
    const float* sW = sm + W_OFF_;
    const int row1 = tid >> 3, c41 = (tid & 7)*4;
    const int f2 = tid + 256;
    const int row2 = f2 >> 3, c42 = (f2 & 7)*4;
    #pragma unroll
    for (int p = 0; p < 3; p++){
        unsigned sb = sbase + (unsigned)((p & 3)*RING_SLOT_)*4u;
        cpa16(sb + (unsigned)(row1*36 + c41)*4u, Ag + (size_t)row1*lda + p*32 + c41);
        cpa16(sb + (unsigned)(row2*36 + c42)*4u, Ag + (size_t)row2*lda + p*32 + c42);
        CP_COMMIT();
    }
    #pragma unroll 1
    for (int s = 0; s < NST; s++){
        CP_WAIT2();
        __syncthreads();
        if (s + 3 < NST){
            int p = s + 3;
            unsigned sb = sbase + (unsigned)((p & 3)*RING_SLOT_)*4u;
            cpa16(sb + (unsigned)(row1*36 + c41)*4u, Ag + (size_t)row1*lda + p*32 + c41);
            cpa16(sb + (unsigned)(row2*36 + c42)*4u, Ag + (size_t)row2*lda + p*32 + c42);
        }
        CP_COMMIT();
        mma_step_resB<LB>(sm + (s & 3)*RING_SLOT_, sW, s*32, m0w, n0w, g, tg, acc);
    }
    CP_WAIT0();
    __syncthreads();
}

// ---------------- persistent recurrent kernel ----------------
__global__ void __launch_bounds__(256, 1) persist_kernel(
    const float* __restrict__ input_q, const float* __restrict__ mask_q,
    const float* __restrict__ mask_p,  const float* __restrict__ b_att,
    const float* __restrict__ w_att,   float* __restrict__ out, int nctas)
{
    extern __shared__ float sm[];
    const int tid = threadIdx.x, bid = blockIdx.x;
    const int lane = tid & 31, warp = tid >> 5;
    const int g = lane >> 2, tg = lane & 3;
    const int m0w = (warp & 1)*32, n0w = (warp >> 1)*16;
    const int p3base = nctas - 64;
    const bool isP1 = (bid < 80);
    const bool isP3 = (bid >= p3base);
    const unsigned sbase = (unsigned)__cvta_generic_to_shared(sm);

    float wv[8];
    #pragma unroll
    for (int i = 0; i < 8; i++) wv[i] = w_att[lane + i*32];

    // preload resident weight tiles (once per launch)
    if (isP1){
        const int n0 = (bid % 20)*64;
        float* sW = sm + W_OFF_;
        for (int i = tid; i < 64*64; i += 256){
            int r = i >> 6, c4 = (i & 63)*4;
            *(float4*)(sW + r*260 + c4) = *(const float4*)(d_W2T + (size_t)(n0+r)*H_ + c4);
        }
    }
    if (isP3){
        const int j0 = ((bid - p3base) & 15)*64;
        float* sW = sm + W_OFF_;
        for (int i = tid; i < 64*80; i += 256){
            int r = i / 80, c4 = (i % 80)*4;
            *(float4*)(sW + r*324 + c4) = *(const float4*)(d_WqT2 + (size_t)(j0+r)*KP_ + c4);
        }
    }
    // init state (every launch/replay)
    for (int i = bid*256 + tid; i < B_*H_; i += nctas*256){ d_h[i] = 0.f; d_c[i] = 0.f; }
    for (int i = bid*256 + tid; i < B_*KP_; i += nctas*256) d_ctx[i] = 0.f;
    grid_bar(nctas);

    for (int st = 0; st < TP_; st++){

        // ======== P1: [hWr | hWhh] = h @ W2T^T, fixed tile per CTA (bids 0..79) ========
        if (isP1){
            const int b0 = (bid / 20)*64, n0 = (bid % 20)*64;
            float acc[2][2][4] = {};
            gemm_ring<260, 8>(d_h + (size_t)b0*H_, H_, sm, sbase, tid, m0w, n0w, g, tg, acc);
            const bool isR = (n0 < H_);
            #pragma unroll
            for (int fm = 0; fm < 2; fm++)
                #pragma unroll
                for (int fn = 0; fn < 2; fn++){
                    int r = b0 + m0w + fm*16 + g;
                    int c = n0 + n0w + fn*8 + tg*2;
                    if (isR){
                        float ba0 = b_att[c], ba1 = b_att[c+1];
                        *(float2*)(d_hWr + r*H_ + c)     = make_float2(acc[fm][fn][0]+ba0, acc[fm][fn][1]+ba1);
                        *(float2*)(d_hWr + (r+8)*H_ + c) = make_float2(acc[fm][fn][2]+ba0, acc[fm][fn][3]+ba1);
                    } else {
                        int j = c - H_;
                        *(float2*)(d_hWhh + (size_t)r*G4_ + j)     = make_float2(acc[fm][fn][0], acc[fm][fn][1]);
                        *(float2*)(d_hWhh + (size_t)(r+8)*G4_ + j) = make_float2(acc[fm][fn][2], acc[fm][fn][3]);
                    }
                }
        }
        grid_bar(nctas);

        // ======== P2: attention, static partition over all CTAs ========
        {
            float* att = sm;
            float* sSc = sm + 256;
            float* sAl = sm + 320;
            for (int b = bid; b < B_; b += nctas){
                __syncthreads();
                att[tid] = d_hWr[b*H_ + tid] + d_pW[((size_t)st*B_ + b)*H_ + tid];
                __syncthreads();
                for (int tq = warp; tq < TQ_; tq += 8){
                    const float* qp = d_qproj + (size_t)(b*TQ_ + tq)*H_;
                    float s = 0.f;
                    #pragma unroll
                    for (int i = 0; i < 8; i++){
                        int h = lane + i*32;
                        s += tanha(qp[h] + att[h]) * wv[i];
                    }
                    #pragma unroll
                    for (int off = 16; off; off >>= 1)
                        s += __shfl_xor_sync(0xffffffffu, s, off);
                    if (lane == 0) sSc[tq] = s;
                }
                __syncthreads();
                if (tid < 32){
                    float s0 = sSc[tid], s1 = sSc[tid+32];
                    if (!(mask_q[b*TQ_ + tid]      > 0.f)) s0 = -1e9f;
                    if (!(mask_q[b*TQ_ + tid + 32] > 0.f)) s1 = -1e9f;
                    float mx = fmaxf(s0, s1);
                    #pragma unroll
                    for (int off = 16; off; off >>= 1)
                        mx = fmaxf(mx, __shfl_xor_sync(0xffffffffu, mx, off));
                    float e0 = __expf(s0 - mx), e1 = __expf(s1 - mx);
                    float sum = e0 + e1;
                    #pragma unroll
                    for (int off = 16; off; off >>= 1)
                        sum += __shfl_xor_sync(0xffffffffu, sum, off);
                    float inv = __frcp_rn(sum);
                    sAl[tid]      = e0 * inv;
                    sAl[tid + 32] = e1 * inv;
                }
                __syncthreads();
                for (int d = tid; d < DPQ_; d += 256){
                    float s = 0.f;
                    const float* iq = input_q + (size_t)b*TQ_*DPQ_ + d;
                    #pragma unroll 8
                    for (int tq = 0; tq < TQ_; tq++)
                        s += sAl[tq] * iq[tq*DPQ_];
                    d_ctx[b*KP_ + d] = s;
                }
                __syncthreads();
            }
        }
        grid_bar(nctas);

        // ======== P3: gates GEMM + fused LSTM, fixed tile per CTA (bids p3base..) ========
        if (isP3){
            const int p = bid - p3base;
            const int b0 = (p >> 4)*64, j0 = (p & 15)*64;
            float acc[2][2][4] = {};
            gemm_ring<324, 10>(d_ctx + (size_t)b0*KP_, KP_, sm, sbase, tid, m0w, n0w, g, tg, acc);
            float* sG = sm + SG_OFF_;
            #pragma unroll
            for (int fm = 0; fm < 2; fm++)
                #pragma unroll
                for (int fn = 0; fn < 2; fn++){
                    int rl = m0w + fm*16 + g;
                    int cl = n0w + fn*8 + tg*2;
                    sG[rl*68 + cl]         = acc[fm][fn][0];
                    sG[rl*68 + cl + 1]     = acc[fm][fn][1];
                    sG[(rl+8)*68 + cl]     = acc[fm][fn][2];
                    sG[(rl+8)*68 + cl + 1] = acc[fm][fn][3];
                }
            __syncthreads();
            #pragma unroll
            for (int u = 0; u < 4; u++){
                int idx = tid + u*256;          // 64 b x 16 h
                int bl = idx >> 4, hl = idx & 15;
                int b = b0 + bl;
                int j = j0 + hl*4;
                int hg = (j0 >> 2) + hl;
                float4 gm = *(float4*)(sG + bl*68 + hl*4);
                float4 pp = __ldcs((const float4*)(d_ppre + ((size_t)st*B_ + b)*G4_ + j));
                float4 hh = *(const float4*)(d_hWhh + (size_t)b*G4_ + j);
                float4 bbv = *(const float4*)(d_bias + j);
                float gi = gm.x + pp.x + hh.x + bbv.x;
                float gf = gm.y + pp.y + hh.y + bbv.y;
                float gg = gm.z + pp.z + hh.z + bbv.z;
                float go = gm.w + pp.w + hh.w + bbv.w;
                float ig = sigm2(gi), fg = sigm2(gf);
                float gt = tanha(gg), og = sigm2(go);
                float c_old = d_c[b*H_ + hg];
                float h_old = d_h[b*H_ + hg];
                float c_new = fg*c_old + ig*gt;
                float h_new = og * tanha(c_new);
                float m = mask_p[b*TP_ + st];
                h_new = h_new*m + h_old*(1.f - m);
                c_new = c_new*m + c_old*(1.f - m);
                d_h[b*H_ + hg] = h_new;
                d_c[b*H_ + hg] = c_new;
                out[((size_t)b*TP_ + st)*H_ + hg] = h_new;
            }
        }
        grid_bar(nctas);
    }
}

// ---------------- launch ----------------
extern "C" void kernel_launch(void* const* d_in, const int* in_sizes, int n_in,
                              void* d_out, int out_size) {
    const float* input_p = (const float*)d_in[0];
    const float* mask_p  = (const float*)d_in[1];
    const float* input_q = (const float*)d_in[2];
    const float* mask_q  = (const float*)d_in[3];
    const float* Wq      = (const float*)d_in[4];
    const float* Wp      = (const float*)d_in[5];
    const float* Wr      = (const float*)d_in[6];
    const float* b_att   = (const float*)d_in[7];
    const float* w_att   = (const float*)d_in[8];
    const float* W_ih    = (const float*)d_in[9];
    const float* W_hh    = (const float*)d_in[10];
    const float* b_ih    = (const float*)d_in[11];
    const float* b_hh    = (const float*)d_in[12];
    float* out = (float*)d_out;

    int dev = 0; cudaGetDevice(&dev);
    int nsm = 0; cudaDeviceGetAttribute(&nsm, cudaDevAttrMultiProcessorCount, dev);
    if (nsm < 144) nsm = 148;   // need >=144 so P1 (80) and P3 (last 64) are disjoint
    if (nsm > 256) nsm = 256;

    float *p_qproj, *p_pW, *p_ppre, *p_WqTn, *p_WpTn, *p_WihpT2;
    cudaGetSymbolAddress((void**)&p_qproj,   d_qproj);
    cudaGetSymbolAddress((void**)&p_pW,      d_pW);
    cudaGetSymbolAddress((void**)&p_ppre,    d_ppre);
    cudaGetSymbolAddress((void**)&p_WqTn,    d_WqTn);
    cudaGetSymbolAddress((void**)&p_WpTn,    d_WpTn);
    cudaGetSymbolAddress((void**)&p_WihpT2,  d_WihpT2);

    cudaFuncSetAttribute(persist_kernel, cudaFuncAttributeMaxDynamicSharedMemorySize,
                         SMEM_FLOATS_*4);

    prep_kernel<<<512, 256>>>(Wq, Wp, Wr, W_ih, W_hh, b_ih, b_hh);

    gemm64_tf32<<<dim3(4, 256), 256>>>(input_q, DPQ_, DPQ_, p_WqTn, KP_, p_qproj, H_, 0);
    gemm64_tf32<<<dim3(4, 2048), 256>>>(input_p, DPQ_, DPQ_, p_WpTn, KP_, p_pW, H_, 1);
    gemm64_tf32<<<dim3(16, 2048), 256>>>(input_p, DPQ_, DPQ_, p_WihpT2, KP_, p_ppre, G4_, 1);

    persist_kernel<<<nsm, 256, SMEM_FLOATS_*4>>>(input_q, mask_q, mask_p,
                                                 b_att, w_att, out, nsm);
}

// round 6
// speedup vs baseline: 2.7711x; 1.0773x over previous
#include <cuda_runtime.h>

#define B_   256
#define TP_  512
#define TQ_  64
#define DPQ_ 300
#define KP_  320     // padded K for 300-dim GEMMs
#define H_   256
#define G4_  1024

// smem layout (floats) for persist kernel
#define RING_SLOT_ 2304        // 64 rows x 36
#define W_OFF_     9216        // after 4 ring slots
#define SG_OFF_    29952       // after P3 weight tile (64*324)
#define SMEM_FLOATS_ 34304     // + sG 64*68 -> 137216 bytes

// ---------------- device scratch ----------------
__device__ float d_qproj[B_*TQ_*H_];        // [b*64+tq][h]
__device__ float d_pW[TP_*B_*H_];           // time-major [st][b][h]
__device__ float d_ppre[TP_*B_*G4_];        // time-major [st][b][j] (permuted gate cols)
__device__ float d_W2T[1280*H_];            // n-major [n][k]; n>=256 = permuted Whh cols
__device__ float d_WqT2[G4_*KP_];           // n-major permuted [j][k], k>=300 zero
__device__ float d_WihpT2[G4_*KP_];
__device__ float d_WqTn[H_*KP_];
__device__ float d_WpTn[H_*KP_];
__device__ float d_bias[G4_];
__device__ float d_hWr[B_*H_];
__device__ float d_hWhh[B_*G4_];
__device__ float d_ctx[B_*KP_];
__device__ float d_h[B_*H_];
__device__ float d_c[B_*H_];
__device__ unsigned g_cnt;
__device__ unsigned g_gen;
__device__ unsigned d_flags[256];

// ---------------- helpers ----------------
__device__ __forceinline__ float tanha(float x){
    float y; asm("tanh.approx.f32 %0, %1;" : "=f"(y) : "f"(x)); return y;
}
__device__ __forceinline__ float sigm2(float x){
    return fmaf(tanha(0.5f*x), 0.5f, 0.5f);
}
__device__ __forceinline__ float to_tf32(float x){
    unsigned u; asm("cvt.rna.tf32.f32 %0, %1;" : "=r"(u) : "f"(x));
    return __uint_as_float(u);
}
__device__ __forceinline__ void mma8(float* d, unsigned a0, unsigned a1, unsigned a2, unsigned a3,
                                     unsigned b0, unsigned b1){
    asm volatile("mma.sync.aligned.m16n8k8.row.col.f32.tf32.tf32.f32 "
                 "{%0,%1,%2,%3},{%4,%5,%6,%7},{%8,%9},{%0,%1,%2,%3};"
                 : "+f"(d[0]), "+f"(d[1]), "+f"(d[2]), "+f"(d[3])
                 : "r"(a0), "r"(a1), "r"(a2), "r"(a3), "r"(b0), "r"(b1));
}
__device__ __forceinline__ void cpa16(unsigned s, const float* g){
    asm volatile("cp.async.cg.shared.global [%0], [%1], 16;" :: "r"(s), "l"(g));
}
#define CP_COMMIT() asm volatile("cp.async.commit_group;" ::: "memory")
#define CP_WAIT2()  asm volatile("cp.async.wait_group 2;"  ::: "memory")
#define CP_WAIT0()  asm volatile("cp.async.wait_group 0;"  ::: "memory")

__device__ __forceinline__ void pref_l2(const float* p){
    asm volatile("prefetch.global.L2 [%0];" :: "l"(p));
}
__device__ __forceinline__ unsigned ldacq(const unsigned* p){
    unsigned v; asm volatile("ld.acquire.gpu.global.u32 %0, [%1];" : "=r"(v) : "l"(p) : "memory");
    return v;
}
// all threads wait until flags[lo..lo+n) >= tok (warp0 scans, CTA syncs)
__device__ __forceinline__ void wait_ge(int lo, int n, unsigned tok){
    if (threadIdx.x < 32){
        for(;;){
            bool ok = true;
            for (int i = (int)threadIdx.x; i < n; i += 32)
                if (ldacq(&d_flags[lo+i]) < tok) ok = false;
            if (__all_sync(0xffffffffu, ok)) break;
            __nanosleep(40);
        }
    }
    __syncthreads();
}
__device__ __forceinline__ void set_flag(int bid, unsigned tok){
    __syncthreads();
    if (threadIdx.x == 0)
        asm volatile("st.release.gpu.global.u32 [%0], %1;" :: "l"(&d_flags[bid]), "r"(tok) : "memory");
}

// ---------------- PROVEN grid barrier (used once, post-init) ----------------
__device__ __forceinline__ void grid_bar(int nctas){
    __syncthreads();
    if (threadIdx.x == 0){
        __threadfence();
        unsigned g = *(volatile unsigned*)&g_gen;
        unsigned prev = atomicAdd(&g_cnt, 1u);
        if (prev == (unsigned)(nctas - 1)){
            atomicExch(&g_cnt, 0u);
            __threadfence();
            atomicAdd(&g_gen, 1u);
        } else {
            while (*(volatile unsigned*)&g_gen == g) { __nanosleep(32); }
        }
        __threadfence();
    }
    __syncthreads();
}

// gate-column permutation: j -> actual gate column
__device__ __forceinline__ int gperm(int j){ return (j & 3)*H_ + (j >> 2); }

// ---------------- K0: weight prep ----------------
__global__ void prep_kernel(const float* __restrict__ Wq, const float* __restrict__ Wp,
                            const float* __restrict__ Wr, const float* __restrict__ Wih,
                            const float* __restrict__ Whh,
                            const float* __restrict__ bih, const float* __restrict__ bhh){
    int idx0 = blockIdx.x*blockDim.x + threadIdx.x;
    int stride = gridDim.x*blockDim.x;
    for (int i = idx0; i < 1280*H_; i += stride){
        int n = i / H_, k = i - n*H_;
        float v = (n < H_) ? Wr[k*H_ + n] : Whh[gperm(n - H_)*H_ + k];
        d_W2T[i] = to_tf32(v);
    }
    for (int i = idx0; i < G4_*KP_; i += stride){
        int j = i / KP_, k = i - j*KP_;
        int a = gperm(j);
        d_WqT2[i]   = (k < DPQ_) ? to_tf32(Wih[a*600 + 300 + k]) : 0.f;
        d_WihpT2[i] = (k < DPQ_) ? to_tf32(Wih[a*600 + k])       : 0.f;
    }
    for (int i = idx0; i < H_*KP_; i += stride){
        int n = i / KP_, k = i - n*KP_;
        d_WqTn[i] = (k < DPQ_) ? to_tf32(Wq[k*H_ + n]) : 0.f;
        d_WpTn[i] = (k < DPQ_) ? to_tf32(Wp[k*H_ + n]) : 0.f;
    }
    for (int j = idx0; j < G4_; j += stride){
        int a = gperm(j);
        d_bias[j] = bih[a] + bhh[a];
    }
}

// ---------------- reset flags (per launch/replay; graph-safe) ----------------
__global__ void reset_kernel(){
    if (blockIdx.x == 0 && threadIdx.x < 256) d_flags[threadIdx.x] = 0u;
}

// ---------------- upfront tf32 GEMM (unchanged, proven) ----------------
__device__ __forceinline__ void stage_load(const float* __restrict__ Ag, int lda,
                                           const float* __restrict__ Bg, int ldb,
                                           float* sA, float* sB, int tid, int krem){
    #pragma unroll
    for (int i = 0; i < 2; i++){
        int f = tid + i*256;
        int row = f >> 3, c4 = (f & 7)*4;
        float4 va = make_float4(0.f,0.f,0.f,0.f);
        if (c4 < krem) va = *(const float4*)(Ag + (size_t)row*lda + c4);
        *(float4*)(sA + row*36 + c4) = va;
        float4 vb = *(const float4*)(Bg + (size_t)row*ldb + c4);
        *(float4*)(sB + row*36 + c4) = vb;
    }
}
__device__ __forceinline__ void mma_tile_step(const float* sA, const float* sB,
                                              int m0w, int n0w, int g, int tg,
                                              float acc[2][2][4]){
    #pragma unroll
    for (int kk = 0; kk < 32; kk += 8){
        const float* pa = sA + kk + tg;
        const float* pb = sB + kk + tg;
        unsigned a00 = __float_as_uint(pa[(m0w+g)*36]);
        unsigned a01 = __float_as_uint(pa[(m0w+g+8)*36]);
        unsigned a02 = __float_as_uint(pa[(m0w+g)*36 + 4]);
        unsigned a03 = __float_as_uint(pa[(m0w+g+8)*36 + 4]);
        unsigned a10 = __float_as_uint(pa[(m0w+16+g)*36]);
        unsigned a11 = __float_as_uint(pa[(m0w+24+g)*36]);
        unsigned a12 = __float_as_uint(pa[(m0w+16+g)*36 + 4]);
        unsigned a13 = __float_as_uint(pa[(m0w+24+g)*36 + 4]);
        unsigned b00 = __float_as_uint(pb[(n0w+g)*36]);
        unsigned b01 = __float_as_uint(pb[(n0w+g)*36 + 4]);
        unsigned b10 = __float_as_uint(pb[(n0w+8+g)*36]);
        unsigned b11 = __float_as_uint(pb[(n0w+8+g)*36 + 4]);
        mma8(acc[0][0], a00,a01,a02,a03, b00,b01);
        mma8(acc[0][1], a00,a01,a02,a03, b10,b11);
        mma8(acc[1][0], a10,a11,a12,a13, b00,b01);
        mma8(acc[1][1], a10,a11,a12,a13, b10,b11);
    }
}
__global__ void __launch_bounds__(256) gemm64_tf32(const float* __restrict__ A, int lda, int K,
                                                   const float* __restrict__ BT, int ldb,
                                                   float* __restrict__ C, int N, int mode){
    __shared__ float sA[64*36];
    __shared__ float sB[64*36];
    const int tid = threadIdx.x, lane = tid & 31, warp = tid >> 5;
    const int g = lane >> 2, tg = lane & 3;
    const int m0 = blockIdx.y*64, n0 = blockIdx.x*64;
    const int m0w = (warp & 1)*32, n0w = (warp >> 1)*16;
    float acc[2][2][4] = {};
    const int nst = (K + 31)/32;
    for (int s = 0; s < nst; s++){
        int k0 = s*32;
        __syncthreads();
        stage_load(A + (size_t)m0*lda + k0, lda, BT + (size_t)n0*ldb + k0, ldb,
                   sA, sB, tid, K - k0);
        __syncthreads();
        mma_tile_step(sA, sB, m0w, n0w, g, tg, acc);
    }
    #pragma unroll
    for (int fm = 0; fm < 2; fm++)
        #pragma unroll
        for (int fn = 0; fn < 2; fn++){
            int r = m0 + m0w + fm*16 + g;
            int c = n0 + n0w + fn*8 + tg*2;
            int m1 = r, m2 = r + 8;
            if (mode){
                m1 = (r & (TP_-1))*B_ + (r >> 9);
                m2 = ((r+8) & (TP_-1))*B_ + ((r+8) >> 9);
            }
            *(float2*)(C + (size_t)m1*N + c) = make_float2(acc[fm][fn][0], acc[fm][fn][1]);
            *(float2*)(C + (size_t)m2*N + c) = make_float2(acc[fm][fn][2], acc[fm][fn][3]);
        }
}

// ---------------- resident-B mma + cp.async ring GEMM ----------------
template<int LB>
__device__ __forceinline__ void mma_step_resB(const float* sAslot, const float* sW, int koff,
                                              int m0w, int n0w, int g, int tg, float acc[2][2][4]){
    #pragma unroll
    for (int kk = 0; kk < 32; kk += 8){
        const float* pa = sAslot + kk + tg;
        const float* pb = sW + koff + kk + tg;
        unsigned a00 = __float_as_uint(pa[(m0w+g)*36]);
        unsigned a01 = __float_as_uint(pa[(m0w+g+8)*36]);
        unsigned a02 = __float_as_uint(pa[(m0w+g)*36 + 4]);
        unsigned a03 = __float_as_uint(pa[(m0w+g+8)*36 + 4]);
        unsigned a10 = __float_as_uint(pa[(m0w+16+g)*36]);
        unsigned a11 = __float_as_uint(pa[(m0w+24+g)*36]);
        unsigned a12 = __float_as_uint(pa[(m0w+16+g)*36 + 4]);
        unsigned a13 = __float_as_uint(pa[(m0w+24+g)*36 + 4]);
        unsigned b00 = __float_as_uint(pb[(n0w+g)*LB]);
        unsigned b01 = __float_as_uint(pb[(n0w+g)*LB + 4]);
        unsigned b10 = __float_as_uint(pb[(n0w+8+g)*LB]);
        unsigned b11 = __float_as_uint(pb[(n0w+8+g)*LB + 4]);
        mma8(acc[0][0], a00,a01,a02,a03, b00,b01);
        mma8(acc[0][1], a00,a01,a02,a03, b10,b11);
        mma8(acc[1][0], a10,a11,a12,a13, b00,b01);
        mma8(acc[1][1], a10,a11,a12,a13, b10,b11);
    }
}

template<int LB, int NST>
__device__ __forceinline__ void gemm_ring(const float* __restrict__ Ag, int lda,
                                          float* sm, unsigned sbase, int tid,
                                          int m0w, int n0w, int g, int tg, float acc[2][2][4]){
    const float* sW = sm + W_OFF_;
    const int row1 = tid >> 3, c41 = (tid & 7)*4;
    const int f2 = tid + 256;
    const int row2 = f2 >> 3, c42 = (f2 & 7)*4;
    #pragma unroll
    for (int p = 0; p < 3; p++){
        unsigned sb = sbase + (unsigned)((p & 3)*RING_SLOT_)*4u;
        cpa16(sb + (unsigned)(row1*36 + c41)*4u, Ag + (size_t)row1*lda + p*32 + c41);
        cpa16(sb + (unsigned)(row2*36 + c42)*4u, Ag + (size_t)row2*lda + p*32 + c42);
        CP_COMMIT();
    }
    #pragma unroll 1
    for (int s = 0; s < NST; s++){
        CP_WAIT2();
        __syncthreads();
        if (s + 3 < NST){
            int p = s + 3;
            unsigned sb = sbase + (unsigned)((p & 3)*RING_SLOT_)*4u;
            cpa16(sb + (unsigned)(row1*36 + c41)*4u, Ag + (size_t)row1*lda + p*32 + c41);
            cpa16(sb + (unsigned)(row2*36 + c42)*4u, Ag + (size_t)row2*lda + p*32 + c42);
        }
        CP_COMMIT();
        mma_step_resB<LB>(sm + (s & 3)*RING_SLOT_, sW, s*32, m0w, n0w, g, tg, acc);
    }
    CP_WAIT0();
    __syncthreads();
}

// ---------------- persistent recurrent kernel ----------------
// P1 tiles: bids 0..15 -> hWr (b0=(bid>>2)*64, n0=(bid&3)*64)
//           bids 16..79 -> hWhh (idx=bid-16: b0=(idx>>4)*64, j0=(idx&15)*64)
// P3 tiles: last 64 bids.
__global__ void __launch_bounds__(256, 1) persist_kernel(
    const float* __restrict__ input_q, const float* __restrict__ mask_q,
    const float* __restrict__ mask_p,  const float* __restrict__ b_att,
    const float* __restrict__ w_att,   float* __restrict__ out, int nctas)
{
    extern __shared__ float sm[];
    const int tid = threadIdx.x, bid = blockIdx.x;
    const int lane = tid & 31, warp = tid >> 5;
    const int g = lane >> 2, tg = lane & 3;
    const int m0w = (warp & 1)*32, n0w = (warp >> 1)*16;
    const int p3base = nctas - 64;
    const bool isP1 = (bid < 80);
    const bool isR  = (bid < 16);
    const bool isP3 = (bid >= p3base);
    const unsigned sbase = (unsigned)__cvta_generic_to_shared(sm);

    // P1 tile coords
    int p1_b0 = 0, p1_n0 = 0;
    if (isP1){
        if (isR){ p1_b0 = (bid >> 2)*64; p1_n0 = (bid & 3)*64; }
        else    { int idx = bid - 16; p1_b0 = (idx >> 4)*64; p1_n0 = H_ + (idx & 15)*64; }
    }
    // P3 tile coords
    int p3_b0 = 0, p3_j0 = 0;
    if (isP3){
        int p = bid - p3base; p3_b0 = (p >> 4)*64; p3_j0 = (p & 15)*64;
    }

    float wv[8];
    #pragma unroll
    for (int i = 0; i < 8; i++) wv[i] = w_att[lane + i*32];

    // preload resident weight tiles (once per launch)
    if (isP1){
        float* sW = sm + W_OFF_;
        for (int i = tid; i < 64*64; i += 256){
            int r = i >> 6, c4 = (i & 63)*4;
            *(float4*)(sW + r*260 + c4) = *(const float4*)(d_W2T + (size_t)(p1_n0+r)*H_ + c4);
        }
    }
    if (isP3){
        float* sW = sm + W_OFF_;
        for (int i = tid; i < 64*80; i += 256){
            int r = i / 80, c4 = (i % 80)*4;
            *(float4*)(sW + r*324 + c4) = *(const float4*)(d_WqT2 + (size_t)(p3_j0+r)*KP_ + c4);
        }
    }
    // init state (every launch/replay)
    for (int i = bid*256 + tid; i < B_*H_; i += nctas*256){ d_h[i] = 0.f; d_c[i] = 0.f; }
    for (int i = bid*256 + tid; i < B_*KP_; i += nctas*256) d_ctx[i] = 0.f;
    grid_bar(nctas);

    for (int st = 0; st < TP_; st++){
        const unsigned base = 3u*(unsigned)st;

        // ---- L2 prefetch of this step's cold slabs (overlaps the waits) ----
        {
            const float* pwb = d_pW + (size_t)st*B_*H_;
            for (int b = bid; b < B_; b += nctas)
                if (tid < 8) pref_l2(pwb + b*H_ + tid*32);
            if (isP3 && tid < 128){
                pref_l2(d_ppre + ((size_t)st*B_ + p3_b0 + (tid >> 1))*G4_
                        + p3_j0 + (tid & 1)*32);
            }
        }

        // ======== P1 ========
        if (isP1){
            wait_ge(p3base, 64, base);      // h from prev step ready
            float acc[2][2][4] = {};
            gemm_ring<260, 8>(d_h + (size_t)p1_b0*H_, H_, sm, sbase, tid, m0w, n0w, g, tg, acc);
            #pragma unroll
            for (int fm = 0; fm < 2; fm++)
                #pragma unroll
                for (int fn = 0; fn < 2; fn++){
                    int r = p1_b0 + m0w + fm*16 + g;
                    int c = p1_n0 + n0w + fn*8 + tg*2;
                    if (isR){
                        float ba0 = b_att[c], ba1 = b_att[c+1];
                        *(float2*)(d_hWr + r*H_ + c)     = make_float2(acc[fm][fn][0]+ba0, acc[fm][fn][1]+ba1);
                        *(float2*)(d_hWr + (r+8)*H_ + c) = make_float2(acc[fm][fn][2]+ba0, acc[fm][fn][3]+ba1);
                    } else {
                        int j = c - H_;
                        *(float2*)(d_hWhh + (size_t)r*G4_ + j)     = make_float2(acc[fm][fn][0], acc[fm][fn][1]);
                        *(float2*)(d_hWhh + (size_t)(r+8)*G4_ + j) = make_float2(acc[fm][fn][2], acc[fm][fn][3]);
                    }
                }
            if (isR) set_flag(bid, base + 1);
        }

        // ======== P2: attention (all CTAs, static partition) ========
        wait_ge(0, 16, base + 1);
        {
            float* att = sm;
            float* sSc = sm + 256;
            float* sAl = sm + 320;
            for (int b = bid; b < B_; b += nctas){
                __syncthreads();
                att[tid] = __ldcg(&d_hWr[b*H_ + tid]) + d_pW[((size_t)st*B_ + b)*H_ + tid];
                __syncthreads();
                float av[8];
                #pragma unroll
                for (int i = 0; i < 8; i++) av[i] = att[lane + i*32];
                #pragma unroll
                for (int it = 0; it < 8; it++){
                    int tq = warp + it*8;
                    const float* qp = d_qproj + (size_t)(b*TQ_ + tq)*H_;
                    float s = 0.f;
                    #pragma unroll
                    for (int i = 0; i < 8; i++)
                        s += tanha(qp[lane + i*32] + av[i]) * wv[i];
                    #pragma unroll
                    for (int off = 16; off; off >>= 1)
                        s += __shfl_xor_sync(0xffffffffu, s, off);
                    if (lane == 0) sSc[tq] = s;
                }
                __syncthreads();
                if (tid < 32){
                    float s0 = sSc[tid], s1 = sSc[tid+32];
                    if (!(mask_q[b*TQ_ + tid]      > 0.f)) s0 = -1e9f;
                    if (!(mask_q[b*TQ_ + tid + 32] > 0.f)) s1 = -1e9f;
                    float mx = fmaxf(s0, s1);
                    #pragma unroll
                    for (int off = 16; off; off >>= 1)
                        mx = fmaxf(mx, __shfl_xor_sync(0xffffffffu, mx, off));
                    float e0 = __expf(s0 - mx), e1 = __expf(s1 - mx);
                    float sum = e0 + e1;
                    #pragma unroll
                    for (int off = 16; off; off >>= 1)
                        sum += __shfl_xor_sync(0xffffffffu, sum, off);
                    float inv = __frcp_rn(sum);
                    sAl[tid]      = e0 * inv;
                    sAl[tid + 32] = e1 * inv;
                }
                __syncthreads();
                for (int d = tid; d < DPQ_; d += 256){
                    float s = 0.f;
                    const float* iq = input_q + (size_t)b*TQ_*DPQ_ + d;
                    #pragma unroll 8
                    for (int tq = 0; tq < TQ_; tq++)
                        s += sAl[tq] * iq[tq*DPQ_];
                    d_ctx[b*KP_ + d] = s;
                }
                __syncthreads();
            }
        }
        set_flag(bid, base + 2);

        // ======== P3: gates GEMM + fused LSTM (last 64 CTAs) ========
        if (isP3){
            wait_ge(0, nctas, base + 2);
            float acc[2][2][4] = {};
            gemm_ring<324, 10>(d_ctx + (size_t)p3_b0*KP_, KP_, sm, sbase, tid, m0w, n0w, g, tg, acc);
            float* sG = sm + SG_OFF_;
            #pragma unroll
            for (int fm = 0; fm < 2; fm++)
                #pragma unroll
                for (int fn = 0; fn < 2; fn++){
                    int rl = m0w + fm*16 + g;
                    int cl = n0w + fn*8 + tg*2;
                    sG[rl*68 + cl]         = acc[fm][fn][0];
                    sG[rl*68 + cl + 1]     = acc[fm][fn][1];
                    sG[(rl+8)*68 + cl]     = acc[fm][fn][2];
                    sG[(rl+8)*68 + cl + 1] = acc[fm][fn][3];
                }
            __syncthreads();
            #pragma unroll
            for (int u = 0; u < 4; u++){
                int idx = tid + u*256;          // 64 b x 16 h
                int bl = idx >> 4, hl = idx & 15;
                int b = p3_b0 + bl;
                int j = p3_j0 + hl*4;
                int hg = (p3_j0 >> 2) + hl;
                float4 gm = *(float4*)(sG + bl*68 + hl*4);
                float4 pp = __ldcs((const float4*)(d_ppre + ((size_t)st*B_ + b)*G4_ + j));
                float4 hh = __ldcg((const float4*)(d_hWhh + (size_t)b*G4_ + j));
                float4 bbv = *(const float4*)(d_bias + j);
                float gi = gm.x + pp.x + hh.x + bbv.x;
                float gf = gm.y + pp.y + hh.y + bbv.y;
                float gg = gm.z + pp.z + hh.z + bbv.z;
                float go = gm.w + pp.w + hh.w + bbv.w;
                float ig = sigm2(gi), fg = sigm2(gf);
                float gt = tanha(gg), og = sigm2(go);
                float c_old = d_c[b*H_ + hg];
                float h_old = d_h[b*H_ + hg];
                float c_new = fg*c_old + ig*gt;
                float h_new = og * tanha(c_new);
                float m = mask_p[b*TP_ + st];
                h_new = h_new*m + h_old*(1.f - m);
                c_new = c_new*m + c_old*(1.f - m);
                d_h[b*H_ + hg] = h_new;
                d_c[b*H_ + hg] = c_new;
                out[((size_t)b*TP_ + st)*H_ + hg] = h_new;
            }
            set_flag(bid, base + 3);
        }
    }
}

// ---------------- launch ----------------
extern "C" void kernel_launch(void* const* d_in, const int* in_sizes, int n_in,
                              void* d_out, int out_size) {
    const float* input_p = (const float*)d_in[0];
    const float* mask_p  = (const float*)d_in[1];
    const float* input_q = (const float*)d_in[2];
    const float* mask_q  = (const float*)d_in[3];
    const float* Wq      = (const float*)d_in[4];
    const float* Wp      = (const float*)d_in[5];
    const float* Wr      = (const float*)d_in[6];
    const float* b_att   = (const float*)d_in[7];
    const float* w_att   = (const float*)d_in[8];
    const float* W_ih    = (const float*)d_in[9];
    const float* W_hh    = (const float*)d_in[10];
    const float* b_ih    = (const float*)d_in[11];
    const float* b_hh    = (const float*)d_in[12];
    float* out = (float*)d_out;

    int dev = 0; cudaGetDevice(&dev);
    int nsm = 0; cudaDeviceGetAttribute(&nsm, cudaDevAttrMultiProcessorCount, dev);
    if (nsm < 144) nsm = 148;   // need >=144 so P1 (80) and P3 (last 64) are disjoint
    if (nsm > 256) nsm = 256;

    float *p_qproj, *p_pW, *p_ppre, *p_WqTn, *p_WpTn, *p_WihpT2;
    cudaGetSymbolAddress((void**)&p_qproj,   d_qproj);
    cudaGetSymbolAddress((void**)&p_pW,      d_pW);
    cudaGetSymbolAddress((void**)&p_ppre,    d_ppre);
    cudaGetSymbolAddress((void**)&p_WqTn,    d_WqTn);
    cudaGetSymbolAddress((void**)&p_WpTn,    d_WpTn);
    cudaGetSymbolAddress((void**)&p_WihpT2,  d_WihpT2);

    cudaFuncSetAttribute(persist_kernel, cudaFuncAttributeMaxDynamicSharedMemorySize,
                         SMEM_FLOATS_*4);

    prep_kernel<<<512, 256>>>(Wq, Wp, Wr, W_ih, W_hh, b_ih, b_hh);
    reset_kernel<<<1, 256>>>();

    gemm64_tf32<<<dim3(4, 256), 256>>>(input_q, DPQ_, DPQ_, p_WqTn, KP_, p_qproj, H_, 0);
    gemm64_tf32<<<dim3(4, 2048), 256>>>(input_p, DPQ_, DPQ_, p_WpTn, KP_, p_pW, H_, 1);
    gemm64_tf32<<<dim3(16, 2048), 256>>>(input_p, DPQ_, DPQ_, p_WihpT2, KP_, p_ppre, G4_, 1);

    persist_kernel<<<nsm, 256, SMEM_FLOATS_*4>>>(input_q, mask_q, mask_p,
                                                 b_att, w_att, out, nsm);
}